// round 2
// baseline (speedup 1.0000x reference)
#include <cuda_runtime.h>

#define Tt 512
#define Dd 1024
#define Ee 64
#define II 512
#define KK 4
#define NPAIR (Tt*KK)

typedef unsigned long long u64;

// ---- scratch (static device globals; no allocation) ----
__device__ int   g_cnt[Ee];
__device__ int   g_slot[Ee*Tt];          // pair index p = t*4+k, grouped by expert
__device__ float g_topw[NPAIR];          // renormalized top-k weights (deterministic, by (t,k))
__device__ float g_H[NPAIR*II];          // 4 MB   silu(g)*u per pair
__device__ float g_Y[NPAIR*Dd];          // 8 MB   down-proj output per pair

// ---- packed f32x2 helpers (Blackwell FFMA2 path, PTX-only) ----
__device__ __forceinline__ u64 ffma2(u64 a, u64 b, u64 c){
  u64 d; asm("fma.rn.f32x2 %0, %1, %2, %3;" : "=l"(d) : "l"(a), "l"(b), "l"(c)); return d;
}
__device__ __forceinline__ u64 fadd2(u64 a, u64 b){
  u64 d; asm("add.rn.f32x2 %0, %1, %2;" : "=l"(d) : "l"(a), "l"(b)); return d;
}
__device__ __forceinline__ u64 pack2(float lo, float hi){
  u64 d;
  asm("mov.b64 %0, {%1, %2};" : "=l"(d) : "r"(__float_as_uint(lo)), "r"(__float_as_uint(hi)));
  return d;
}
__device__ __forceinline__ float lo2(u64 v){ return __uint_as_float((unsigned)v); }
__device__ __forceinline__ float hi2(u64 v){ return __uint_as_float((unsigned)(v >> 32)); }

__device__ __forceinline__ u64 shfl_xor_u64(u64 v, int m){
  unsigned lo = (unsigned)v, hi = (unsigned)(v >> 32);
  lo = __shfl_xor_sync(0xffffffffu, lo, m);
  hi = __shfl_xor_sync(0xffffffffu, hi, m);
  return ((u64)hi << 32) | lo;
}
__device__ __forceinline__ u64 warp_red2(u64 v){
  #pragma unroll
  for (int m = 16; m; m >>= 1) v = fadd2(v, shfl_xor_u64(v, m));
  return v;
}

// ---- kernel 0: zero expert counters (fresh every replay) ----
__global__ void zero_kernel(){
  if (threadIdx.x < Ee) g_cnt[threadIdx.x] = 0;
}

// ---- kernel 1: router (logits -> softmax -> top4 -> renorm -> group) ----
__global__ void router_kernel(const float* __restrict__ x, const float* __restrict__ gw){
  int t = blockIdx.x;
  __shared__ float xs[Dd];
  __shared__ float lg[Ee];
  for (int i = threadIdx.x; i < Dd/4; i += 64)
    ((float4*)xs)[i] = ((const float4*)(x + (size_t)t*Dd))[i];
  __syncthreads();
  const float* w = gw + (size_t)threadIdx.x * Dd;
  float acc = 0.f;
  #pragma unroll 4
  for (int d = 0; d < Dd; d += 4){
    float4 wv = *(const float4*)(w + d);
    acc += wv.x*xs[d] + wv.y*xs[d+1] + wv.z*xs[d+2] + wv.w*xs[d+3];
  }
  lg[threadIdx.x] = acc;
  __syncthreads();
  if (threadIdx.x == 0){
    float mx = lg[0];
    for (int i = 1; i < Ee; i++) mx = fmaxf(mx, lg[i]);
    for (int i = 0; i < Ee; i++) lg[i] = __expf(lg[i] - mx);
    // softmax denominator cancels in top-k renormalization: use exp values directly
    float wsum = 0.f; int ids[KK]; float ws[KK];
    for (int k = 0; k < KK; k++){
      int bi = 0; float bv = -1.f;
      for (int i = 0; i < Ee; i++){ float v = lg[i]; if (v > bv){ bv = v; bi = i; } }
      ids[k] = bi; ws[k] = bv; lg[bi] = -2.f; wsum += bv;
    }
    float inv = 1.f / wsum;
    for (int k = 0; k < KK; k++){
      int p = t*KK + k;
      g_topw[p] = ws[k] * inv;
      int slot = atomicAdd(&g_cnt[ids[k]], 1);
      g_slot[ids[k]*Tt + slot] = p;
    }
  }
}

// ---- kernel 2: gate+up proj -> H = silu(g)*u, grouped by expert ----
// grid (E, 32): each block = 16 f-rows (8 warps x 2 f), loops over this
// expert's tokens in tiles of 8 staged in shared.
// gate & up are packed into one f32x2 lane: (wg[d], wu[d]) * (x[d], x[d]).
#define GU_TOK 8
__global__ void __launch_bounds__(256,2) gateup_kernel(const float* __restrict__ x,
    const float* __restrict__ wg, const float* __restrict__ wu){
  int e = blockIdx.x;
  int nt = g_cnt[e];
  if (nt == 0) return;
  int warp = threadIdx.x >> 5, lane = threadIdx.x & 31;
  int f0 = blockIdx.y*16 + warp*2;
  __shared__ float xs[GU_TOK][Dd];   // 32 KB
  __shared__ int ps[GU_TOK];
  const float* wg0 = wg + ((size_t)e*II + f0)*Dd;
  const float* wg1 = wg0 + Dd;
  const float* wu0 = wu + ((size_t)e*II + f0)*Dd;
  const float* wu1 = wu0 + Dd;
  for (int t0 = 0; t0 < nt; t0 += GU_TOK){
    int ntile = min(GU_TOK, nt - t0);
    __syncthreads();
    for (int i = threadIdx.x; i < ntile*(Dd/4); i += 256){
      int tt = i / (Dd/4), dd = i % (Dd/4);
      int p = g_slot[e*Tt + t0 + tt];
      if (dd == 0) ps[tt] = p;
      ((float4*)xs[tt])[dd] = ((const float4*)(x + (size_t)(p >> 2)*Dd))[dd];
    }
    __syncthreads();
    u64 acc0[GU_TOK], acc1[GU_TOK];
    #pragma unroll
    for (int tt = 0; tt < GU_TOK; tt++){ acc0[tt] = 0ull; acc1[tt] = 0ull; }
    #pragma unroll 2
    for (int d = lane; d < Dd; d += 32){
      u64 w0 = pack2(wg0[d], wu0[d]);
      u64 w1 = pack2(wg1[d], wu1[d]);
      #pragma unroll
      for (int tt = 0; tt < GU_TOK; tt++){
        float xv = xs[tt][d];
        u64 xv2 = pack2(xv, xv);
        acc0[tt] = ffma2(w0, xv2, acc0[tt]);
        acc1[tt] = ffma2(w1, xv2, acc1[tt]);
      }
    }
    #pragma unroll
    for (int tt = 0; tt < GU_TOK; tt++){
      u64 r0 = warp_red2(acc0[tt]);
      u64 r1 = warp_red2(acc1[tt]);
      if (lane == 0 && tt < ntile){
        int p = ps[tt];
        float g = lo2(r0), u = hi2(r0);
        g_H[(size_t)p*II + f0]     = (g / (1.f + __expf(-g))) * u;
        g = lo2(r1); u = hi2(r1);
        g_H[(size_t)p*II + f0 + 1] = (g / (1.f + __expf(-g))) * u;
      }
    }
  }
}

// ---- kernel 3: down proj -> Y[p][d], grouped by expert ----
// grid (E, 64): block = 16 d-rows (8 warps x 2 d), pair tile of 16 staged H.
// two d-rows packed per f32x2 lane: (wd[d0][f], wd[d1][f]) * (h[f], h[f]).
#define DN_TOK 16
__global__ void __launch_bounds__(256,2) down_kernel(const float* __restrict__ wd){
  int e = blockIdx.x;
  int nt = g_cnt[e];
  if (nt == 0) return;
  int warp = threadIdx.x >> 5, lane = threadIdx.x & 31;
  int d0 = blockIdx.y*16 + warp*2;
  __shared__ float hs[DN_TOK][II];   // 32 KB
  __shared__ int ps[DN_TOK];
  const float* w0 = wd + ((size_t)e*Dd + d0)*II;
  const float* w1 = w0 + II;
  for (int t0 = 0; t0 < nt; t0 += DN_TOK){
    int ntile = min(DN_TOK, nt - t0);
    __syncthreads();
    for (int i = threadIdx.x; i < ntile*(II/4); i += 256){
      int tt = i / (II/4), ff = i % (II/4);
      int p = g_slot[e*Tt + t0 + tt];
      if (ff == 0) ps[tt] = p;
      ((float4*)hs[tt])[ff] = ((const float4*)(g_H + (size_t)p*II))[ff];
    }
    __syncthreads();
    u64 acc[DN_TOK];
    #pragma unroll
    for (int tt = 0; tt < DN_TOK; tt++) acc[tt] = 0ull;
    #pragma unroll 2
    for (int f = lane; f < II; f += 32){
      u64 wv = pack2(w0[f], w1[f]);
      #pragma unroll
      for (int tt = 0; tt < DN_TOK; tt++){
        float hv = hs[tt][f];
        acc[tt] = ffma2(wv, pack2(hv, hv), acc[tt]);
      }
    }
    #pragma unroll
    for (int tt = 0; tt < DN_TOK; tt++){
      u64 r = warp_red2(acc[tt]);
      if (lane == 0 && tt < ntile){
        int p = ps[tt];
        g_Y[(size_t)p*Dd + d0]     = lo2(r);
        g_Y[(size_t)p*Dd + d0 + 1] = hi2(r);
      }
    }
  }
}

// ---- kernel 4: deterministic per-token combine ----
__global__ void combine_kernel(float* __restrict__ out){
  int t = blockIdx.x;
  int i = threadIdx.x;                        // 256 threads, one float4 each
  float w0 = g_topw[t*4+0], w1 = g_topw[t*4+1];
  float w2 = g_topw[t*4+2], w3 = g_topw[t*4+3];
  const float4* y0 = (const float4*)(g_Y + (size_t)(t*4+0)*Dd);
  const float4* y1 = (const float4*)(g_Y + (size_t)(t*4+1)*Dd);
  const float4* y2 = (const float4*)(g_Y + (size_t)(t*4+2)*Dd);
  const float4* y3 = (const float4*)(g_Y + (size_t)(t*4+3)*Dd);
  float4 a = y0[i], b = y1[i], c = y2[i], d = y3[i];
  float4 r;
  r.x = w0*a.x + w1*b.x + w2*c.x + w3*d.x;
  r.y = w0*a.y + w1*b.y + w2*c.y + w3*d.y;
  r.z = w0*a.z + w1*b.z + w2*c.z + w3*d.z;
  r.w = w0*a.w + w1*b.w + w2*c.w + w3*d.w;
  ((float4*)(out + (size_t)t*Dd))[i] = r;
}

extern "C" void kernel_launch(void* const* d_in, const int* in_sizes, int n_in,
                              void* d_out, int out_size){
  const float* x  = (const float*)d_in[0];   // hidden_states [512,1024]
  const float* gw = (const float*)d_in[1];   // gate_w        [64,1024]
  const float* wg = (const float*)d_in[2];   // w_gate        [64,512,1024]
  const float* wu = (const float*)d_in[3];   // w_up          [64,512,1024]
  const float* wd = (const float*)d_in[4];   // w_down        [64,1024,512]
  float* out = (float*)d_out;                // [512,1024] f32
  (void)in_sizes; (void)n_in; (void)out_size;

  zero_kernel<<<1, 64>>>();
  router_kernel<<<Tt, 64>>>(x, gw);
  gateup_kernel<<<dim3(Ee, 32), 256>>>(x, wg, wu);
  down_kernel<<<dim3(Ee, 64), 256>>>(wd);
  combine_kernel<<<Tt, 256>>>(out);
}

// round 3
// speedup vs baseline: 1.4664x; 1.4664x over previous
#include <cuda_runtime.h>

#define Tt 512
#define Dd 1024
#define Ee 64
#define II 512
#define KK 4
#define NPAIR (Tt*KK)

typedef unsigned long long u64;

// ---- scratch (static device globals; no allocation) ----
__device__ int   g_cnt[Ee];
__device__ int   g_slot[Ee*Tt];          // pair index p = t*4+k, grouped by expert
__device__ float g_topw[NPAIR];
__device__ float g_H[NPAIR*II];          // 4 MB
__device__ float g_Y[NPAIR*Dd];          // 8 MB

// ---- packed f32x2 helpers ----
__device__ __forceinline__ u64 ffma2(u64 a, u64 b, u64 c){
  u64 d; asm("fma.rn.f32x2 %0, %1, %2, %3;" : "=l"(d) : "l"(a), "l"(b), "l"(c)); return d;
}
__device__ __forceinline__ u64 pack2(float lo, float hi){
  u64 d;
  asm("mov.b64 %0, {%1, %2};" : "=l"(d) : "r"(__float_as_uint(lo)), "r"(__float_as_uint(hi)));
  return d;
}
__device__ __forceinline__ float lo2(u64 v){ return __uint_as_float((unsigned)v); }
__device__ __forceinline__ float hi2(u64 v){ return __uint_as_float((unsigned)(v >> 32)); }

// ---- GEMM tiling config ----
#define MT 32          // m tile (tokens)
#define NT 256         // n' tile
#define KT 32          // k tile
#define AS_STR 36      // As row stride (floats): 144B, 16B-aligned rows
#define BS_STR 33      // Bs row stride (floats): odd mod 32 -> conflict-free col reads

// ---- kernel 0: zero expert counters ----
__global__ void zero_kernel(){
  if (threadIdx.x < Ee) g_cnt[threadIdx.x] = 0;
}

// ---- kernel 1: router ----
__global__ void router_kernel(const float* __restrict__ x, const float* __restrict__ gw){
  int t = blockIdx.x;
  __shared__ float xs[Dd];
  __shared__ float lg[Ee];
  for (int i = threadIdx.x; i < Dd/4; i += 64)
    ((float4*)xs)[i] = ((const float4*)(x + (size_t)t*Dd))[i];
  __syncthreads();
  const float* w = gw + (size_t)threadIdx.x * Dd;
  float acc = 0.f;
  #pragma unroll 4
  for (int d = 0; d < Dd; d += 4){
    float4 wv = *(const float4*)(w + d);
    acc += wv.x*xs[d] + wv.y*xs[d+1] + wv.z*xs[d+2] + wv.w*xs[d+3];
  }
  lg[threadIdx.x] = acc;
  __syncthreads();
  if (threadIdx.x == 0){
    float mx = lg[0];
    for (int i = 1; i < Ee; i++) mx = fmaxf(mx, lg[i]);
    for (int i = 0; i < Ee; i++) lg[i] = __expf(lg[i] - mx);
    float wsum = 0.f; int ids[KK]; float ws[KK];
    for (int k = 0; k < KK; k++){
      int bi = 0; float bv = -1.f;
      for (int i = 0; i < Ee; i++){ float v = lg[i]; if (v > bv){ bv = v; bi = i; } }
      ids[k] = bi; ws[k] = bv; lg[bi] = -2.f; wsum += bv;
    }
    float inv = 1.f / wsum;
    for (int k = 0; k < KK; k++){
      int p = t*KK + k;
      g_topw[p] = ws[k] * inv;
      int slot = atomicAdd(&g_cnt[ids[k]], 1);
      g_slot[ids[k]*Tt + slot] = p;
    }
  }
}

// ---- kernel 2: gate+up GEMM -> H = silu(g)*u ----
// C[m][n'] over n'=0..1023 interleaved (even n' = gate row f=n'/2, odd = up).
// Thread tile: 4 m-pairs (8 m, packed f32x2 along m) x 4 n' (stride 64).
// (g,u) pairs recombined post-loop via lane shuffle (lanes tn, tn+1).
__global__ void __launch_bounds__(256,2) gateup_kernel(const float* __restrict__ x,
    const float* __restrict__ wg, const float* __restrict__ wu){
  int e = blockIdx.x;
  int nt = g_cnt[e];
  int z = blockIdx.z;
  if (nt <= z*MT) return;
  __shared__ __align__(16) float As[KT*AS_STR];
  __shared__ float Bs[NT*BS_STR];
  __shared__ int sp[MT];
  int tid = threadIdx.x;
  int tm = tid >> 6, tn = tid & 63;
  int f0 = blockIdx.y * (NT/2);        // 128 f-rows per block
  int bb0 = (tn      )*BS_STR;
  int bb1 = (tn +  64)*BS_STR;
  int bb2 = (tn + 128)*BS_STR;
  int bb3 = (tn + 192)*BS_STR;
  int am = tid >> 3, akq = tid & 7;

  for (int t0 = z*MT; t0 < nt; t0 += 2*MT){
    int ntile = min(MT, nt - t0);
    __syncthreads();
    if (tid < MT) sp[tid] = (t0 + tid < nt) ? g_slot[e*Tt + t0 + tid] : 0;
    __syncthreads();
    u64 acc[4][4];
    #pragma unroll
    for (int i = 0; i < 4; i++)
      #pragma unroll
      for (int c = 0; c < 4; c++) acc[i][c] = 0ull;

    for (int k0 = 0; k0 < Dd; k0 += KT){
      // stage A transposed: As[k][m] = x[token(m)][k0+k]
      float4 av = make_float4(0.f,0.f,0.f,0.f);
      if (am < ntile)
        av = *(const float4*)(x + (size_t)(sp[am] >> 2)*Dd + k0 + 4*akq);
      As[(4*akq+0)*AS_STR + am] = av.x;
      As[(4*akq+1)*AS_STR + am] = av.y;
      As[(4*akq+2)*AS_STR + am] = av.z;
      As[(4*akq+3)*AS_STR + am] = av.w;
      // stage B: Bs[n'][k], n' even<-wg, odd<-wu (rows k-contiguous, no transpose)
      #pragma unroll
      for (int jj = 0; jj < 8; jj++){
        int flat = jj*256 + tid;
        int row = flat >> 3, kq = flat & 7;
        const float* src = (row & 1) ? wu : wg;
        float4 bv = *(const float4*)(src + ((size_t)e*II + f0 + (row>>1))*Dd + k0 + 4*kq);
        float* bp = Bs + row*BS_STR + 4*kq;
        bp[0] = bv.x; bp[1] = bv.y; bp[2] = bv.z; bp[3] = bv.w;
      }
      __syncthreads();
      #pragma unroll 8
      for (int k = 0; k < KT; k++){
        ulonglong2 A0 = *(const ulonglong2*)(As + k*AS_STR + 8*tm);
        ulonglong2 A1 = *(const ulonglong2*)(As + k*AS_STR + 8*tm + 4);
        float b0 = Bs[bb0 + k], b1 = Bs[bb1 + k], b2 = Bs[bb2 + k], b3 = Bs[bb3 + k];
        u64 d0 = pack2(b0,b0), d1 = pack2(b1,b1), d2 = pack2(b2,b2), d3 = pack2(b3,b3);
        acc[0][0] = ffma2(A0.x, d0, acc[0][0]);
        acc[0][1] = ffma2(A0.x, d1, acc[0][1]);
        acc[0][2] = ffma2(A0.x, d2, acc[0][2]);
        acc[0][3] = ffma2(A0.x, d3, acc[0][3]);
        acc[1][0] = ffma2(A0.y, d0, acc[1][0]);
        acc[1][1] = ffma2(A0.y, d1, acc[1][1]);
        acc[1][2] = ffma2(A0.y, d2, acc[1][2]);
        acc[1][3] = ffma2(A0.y, d3, acc[1][3]);
        acc[2][0] = ffma2(A1.x, d0, acc[2][0]);
        acc[2][1] = ffma2(A1.x, d1, acc[2][1]);
        acc[2][2] = ffma2(A1.x, d2, acc[2][2]);
        acc[2][3] = ffma2(A1.x, d3, acc[2][3]);
        acc[3][0] = ffma2(A1.y, d0, acc[3][0]);
        acc[3][1] = ffma2(A1.y, d1, acc[3][1]);
        acc[3][2] = ffma2(A1.y, d2, acc[3][2]);
        acc[3][3] = ffma2(A1.y, d3, acc[3][3]);
      }
      __syncthreads();
    }
    // epilogue: combine (g,u) via lane shuffle, apply silu, write H
    #pragma unroll
    for (int i = 0; i < 4; i++){
      #pragma unroll
      for (int c = 0; c < 4; c++){
        unsigned glo = (unsigned)acc[i][c];
        unsigned ghi = (unsigned)(acc[i][c] >> 32);
        unsigned ulo = __shfl_down_sync(0xffffffffu, glo, 1);
        unsigned uhi = __shfl_down_sync(0xffffffffu, ghi, 1);
        if (!(tn & 1)){
          int f = f0 + ((tn + 64*c) >> 1);
          int me = 8*tm + 2*i;
          if (me < ntile){
            float gv = __uint_as_float(glo), uv = __uint_as_float(ulo);
            g_H[(size_t)sp[me]*II + f] = (gv / (1.f + __expf(-gv))) * uv;
          }
          if (me + 1 < ntile){
            float gv = __uint_as_float(ghi), uv = __uint_as_float(uhi);
            g_H[(size_t)sp[me+1]*II + f] = (gv / (1.f + __expf(-gv))) * uv;
          }
        }
      }
    }
  }
}

// ---- kernel 3: down GEMM -> Y[p][d] ----
__global__ void __launch_bounds__(256,2) down_kernel(const float* __restrict__ wd){
  int e = blockIdx.x;
  int nt = g_cnt[e];
  int z = blockIdx.z;
  if (nt <= z*MT) return;
  __shared__ __align__(16) float As[KT*AS_STR];
  __shared__ float Bs[NT*BS_STR];
  __shared__ int sp[MT];
  int tid = threadIdx.x;
  int tm = tid >> 6, tn = tid & 63;
  int n0 = blockIdx.y * NT;
  int bb0 = (tn      )*BS_STR;
  int bb1 = (tn +  64)*BS_STR;
  int bb2 = (tn + 128)*BS_STR;
  int bb3 = (tn + 192)*BS_STR;
  int am = tid >> 3, akq = tid & 7;

  for (int t0 = z*MT; t0 < nt; t0 += 2*MT){
    int ntile = min(MT, nt - t0);
    __syncthreads();
    if (tid < MT) sp[tid] = (t0 + tid < nt) ? g_slot[e*Tt + t0 + tid] : 0;
    __syncthreads();
    u64 acc[4][4];
    #pragma unroll
    for (int i = 0; i < 4; i++)
      #pragma unroll
      for (int c = 0; c < 4; c++) acc[i][c] = 0ull;

    for (int k0 = 0; k0 < II; k0 += KT){
      float4 av = make_float4(0.f,0.f,0.f,0.f);
      if (am < ntile)
        av = *(const float4*)(g_H + (size_t)sp[am]*II + k0 + 4*akq);
      As[(4*akq+0)*AS_STR + am] = av.x;
      As[(4*akq+1)*AS_STR + am] = av.y;
      As[(4*akq+2)*AS_STR + am] = av.z;
      As[(4*akq+3)*AS_STR + am] = av.w;
      #pragma unroll
      for (int jj = 0; jj < 8; jj++){
        int flat = jj*256 + tid;
        int row = flat >> 3, kq = flat & 7;
        float4 bv = *(const float4*)(wd + ((size_t)e*Dd + n0 + row)*II + k0 + 4*kq);
        float* bp = Bs + row*BS_STR + 4*kq;
        bp[0] = bv.x; bp[1] = bv.y; bp[2] = bv.z; bp[3] = bv.w;
      }
      __syncthreads();
      #pragma unroll 8
      for (int k = 0; k < KT; k++){
        ulonglong2 A0 = *(const ulonglong2*)(As + k*AS_STR + 8*tm);
        ulonglong2 A1 = *(const ulonglong2*)(As + k*AS_STR + 8*tm + 4);
        float b0 = Bs[bb0 + k], b1 = Bs[bb1 + k], b2 = Bs[bb2 + k], b3 = Bs[bb3 + k];
        u64 d0 = pack2(b0,b0), d1 = pack2(b1,b1), d2 = pack2(b2,b2), d3 = pack2(b3,b3);
        acc[0][0] = ffma2(A0.x, d0, acc[0][0]);
        acc[0][1] = ffma2(A0.x, d1, acc[0][1]);
        acc[0][2] = ffma2(A0.x, d2, acc[0][2]);
        acc[0][3] = ffma2(A0.x, d3, acc[0][3]);
        acc[1][0] = ffma2(A0.y, d0, acc[1][0]);
        acc[1][1] = ffma2(A0.y, d1, acc[1][1]);
        acc[1][2] = ffma2(A0.y, d2, acc[1][2]);
        acc[1][3] = ffma2(A0.y, d3, acc[1][3]);
        acc[2][0] = ffma2(A1.x, d0, acc[2][0]);
        acc[2][1] = ffma2(A1.x, d1, acc[2][1]);
        acc[2][2] = ffma2(A1.x, d2, acc[2][2]);
        acc[2][3] = ffma2(A1.x, d3, acc[2][3]);
        acc[3][0] = ffma2(A1.y, d0, acc[3][0]);
        acc[3][1] = ffma2(A1.y, d1, acc[3][1]);
        acc[3][2] = ffma2(A1.y, d2, acc[3][2]);
        acc[3][3] = ffma2(A1.y, d3, acc[3][3]);
      }
      __syncthreads();
    }
    #pragma unroll
    for (int i = 0; i < 4; i++){
      int me = 8*tm + 2*i;
      #pragma unroll
      for (int c = 0; c < 4; c++){
        int d = n0 + tn + 64*c;
        if (me < ntile)     g_Y[(size_t)sp[me]*Dd + d]   = lo2(acc[i][c]);
        if (me + 1 < ntile) g_Y[(size_t)sp[me+1]*Dd + d] = hi2(acc[i][c]);
      }
    }
  }
}

// ---- kernel 4: deterministic per-token combine ----
__global__ void combine_kernel(float* __restrict__ out){
  int t = blockIdx.x;
  int i = threadIdx.x;
  float w0 = g_topw[t*4+0], w1 = g_topw[t*4+1];
  float w2 = g_topw[t*4+2], w3 = g_topw[t*4+3];
  const float4* y0 = (const float4*)(g_Y + (size_t)(t*4+0)*Dd);
  const float4* y1 = (const float4*)(g_Y + (size_t)(t*4+1)*Dd);
  const float4* y2 = (const float4*)(g_Y + (size_t)(t*4+2)*Dd);
  const float4* y3 = (const float4*)(g_Y + (size_t)(t*4+3)*Dd);
  float4 a = y0[i], b = y1[i], c = y2[i], d = y3[i];
  float4 r;
  r.x = w0*a.x + w1*b.x + w2*c.x + w3*d.x;
  r.y = w0*a.y + w1*b.y + w2*c.y + w3*d.y;
  r.z = w0*a.z + w1*b.z + w2*c.z + w3*d.z;
  r.w = w0*a.w + w1*b.w + w2*c.w + w3*d.w;
  ((float4*)(out + (size_t)t*Dd))[i] = r;
}

extern "C" void kernel_launch(void* const* d_in, const int* in_sizes, int n_in,
                              void* d_out, int out_size){
  const float* x  = (const float*)d_in[0];
  const float* gw = (const float*)d_in[1];
  const float* wg = (const float*)d_in[2];
  const float* wu = (const float*)d_in[3];
  const float* wd = (const float*)d_in[4];
  float* out = (float*)d_out;
  (void)in_sizes; (void)n_in; (void)out_size;

  zero_kernel<<<1, 64>>>();
  router_kernel<<<Tt, 64>>>(x, gw);
  gateup_kernel<<<dim3(Ee, 4, 2), 256>>>(x, wg, wu);
  down_kernel<<<dim3(Ee, 4, 2), 256>>>(wd);
  combine_kernel<<<Tt, 256>>>(out);
}